// round 1
// baseline (speedup 1.0000x reference)
#include <cuda_runtime.h>
#include <cuda_bf16.h>

// ---------------------------------------------------------------------------
// Hypernetwork_PONG_dense: the reference only ever consumes
//   - w3 branch: batch rows i*64 (i=0..63), W2 column 1
//   - w4 branch: batch rows {0,682,1365,2048,2730,3413}, W2 cols {65,69,67,...}
// Everything else is dead. Output = [tile(sel3,80) | 64 zeros | sel4].
// ---------------------------------------------------------------------------

#define N_H 70
#define SEG3_END   409600   // 80 * 5120
#define ZERO_END   409664   // + 64 zeros
#define OUT_TOTAL  412742   // + 6*513

__device__ float g_h[N_H];  // folded hidden scalars: [0..63] w3 branch, [64..69] w4 branch

__global__ void hidden_kernel(const float* __restrict__ inp,
                              const float* __restrict__ W1,
                              const float* __restrict__ b1,
                              const float* __restrict__ W2,
                              const float* __restrict__ b2,
                              const float* __restrict__ W3a,
                              const float* __restrict__ b3a,
                              const float* __restrict__ W4a,
                              const float* __restrict__ b4a) {
    const int i = blockIdx.x;

    int row, col;
    if (i < 64) {
        row = i * 64;          // x3[i,1] lives at batch row i*64, feature col 1
        col = 1;
    } else {
        const int r4[6] = {0, 682, 1365, 2048, 2730, 3413};
        const int c4[6] = {65, 69, 67, 65, 69, 67};
        row = r4[i - 64];
        col = c4[i - 64];
    }

    // dot(inputs[row], W1) over 6400 fp32 = 1600 float4
    const float4* __restrict__ ip = (const float4*)(inp + (size_t)row * 6400);
    const float4* __restrict__ wp = (const float4*)W1;

    float sum = 0.f;
    for (int j = threadIdx.x; j < 1600; j += 256) {
        float4 a = ip[j];
        float4 w = wp[j];
        sum += a.x * w.x + a.y * w.y + a.z * w.z + a.w * w.w;
    }

    // warp reduce
    #pragma unroll
    for (int off = 16; off; off >>= 1)
        sum += __shfl_down_sync(0xffffffffu, sum, off);

    __shared__ float ws[8];
    if ((threadIdx.x & 31) == 0) ws[threadIdx.x >> 5] = sum;
    __syncthreads();

    if (threadIdx.x == 0) {
        float t = 0.f;
        #pragma unroll
        for (int w = 0; w < 8; w++) t += ws[w];

        float s = fmaxf(t + b1[0], 0.f);                       // layer 1
        float x = fmaxf(fmaf(s, W2[col], b2[col]), 0.f);       // layer 2 (one column)
        float h;
        if (i < 64) h = fmaxf(fmaf(x, W3a[0], b3a[0]), 0.f);   // w3 hidden
        else        h = fmaxf(fmaf(x, W4a[0], b4a[0]), 0.f);   // w4 hidden
        g_h[i] = h;
    }
}

__global__ void output_kernel(const float* __restrict__ W3b,
                              const float* __restrict__ b3b,
                              const float* __restrict__ W4b,
                              const float* __restrict__ b4b,
                              float* __restrict__ out) {
    const int o = (blockIdx.x * 256 + threadIdx.x) * 4;
    if (o >= OUT_TOTAL) return;

    if (o < SEG3_END) {
        // seg3: out[t*5120 + i*80 + k] = relu(h3[i]*W3b[k] + b3b[k])
        // group of 4 stays inside one i (80 % 4 == 0, o % 4 == 0)
        int q = o % 5120;
        int i = q / 80;
        int k = q % 80;
        float  h  = g_h[i];
        float4 w  = ((const float4*)W3b)[k >> 2];
        float4 bb = ((const float4*)b3b)[k >> 2];
        float4 r;
        r.x = fmaxf(fmaf(h, w.x, bb.x), 0.f);
        r.y = fmaxf(fmaf(h, w.y, bb.y), 0.f);
        r.z = fmaxf(fmaf(h, w.z, bb.z), 0.f);
        r.w = fmaxf(fmaf(h, w.w, bb.w), 0.f);
        *(float4*)(out + o) = r;
    } else {
        // zero band + sel4 tail (~3.1K elements): scalar is fine
        #pragma unroll
        for (int e = o; e < o + 4; e++) {
            if (e >= OUT_TOTAL) break;
            if (e < ZERO_END) {
                out[e] = 0.f;
            } else {
                int p = e - ZERO_END;
                int i = p / 513;
                int k = p - i * 513;
                out[e] = fmaxf(fmaf(g_h[64 + i], W4b[k], b4b[k]), 0.f);
            }
        }
    }
}

extern "C" void kernel_launch(void* const* d_in, const int* in_sizes, int n_in,
                              void* d_out, int out_size) {
    const float* inp = (const float*)d_in[0];
    const float* W1  = (const float*)d_in[1];
    const float* b1  = (const float*)d_in[2];
    const float* W2  = (const float*)d_in[3];
    const float* b2  = (const float*)d_in[4];
    const float* W3a = (const float*)d_in[5];
    const float* b3a = (const float*)d_in[6];
    const float* W3b = (const float*)d_in[7];
    const float* b3b = (const float*)d_in[8];
    const float* W4a = (const float*)d_in[9];
    const float* b4a = (const float*)d_in[10];
    const float* W4b = (const float*)d_in[11];
    const float* b4b = (const float*)d_in[12];
    float* out = (float*)d_out;

    hidden_kernel<<<N_H, 256>>>(inp, W1, b1, W2, b2, W3a, b3a, W4a, b4a);

    const int groups = (OUT_TOTAL + 3) / 4;           // 103186
    const int blocks = (groups + 255) / 256;          // 404
    output_kernel<<<blocks, 256>>>(W3b, b3b, W4b, b4b, out);
}